// round 2
// baseline (speedup 1.0000x reference)
#include <cuda_runtime.h>
#include <math.h>

// Problem constants (fixed shapes)
#define NB      128          // batch
#define SS      128          // seq
#define EE      1024         // embed
#define NQ      8            // qubits
#define NL      4            // layers
#define DIMQ    256          // 2^NQ
#define ROWS    16384        // NB*SS
#define Y_SIZE  16777216L    // NB*SS*EE

// Scratch (static device globals — allowed)
__device__ float  d_qin[ROWS * NQ];
__device__ float2 d_gates[NL * NQ * 4];
__device__ int    d_perm[DIMQ];
__device__ float2 d_psi[(long)ROWS * DIMQ];
__device__ float  d_V[(long)ROWS * EE];
__device__ float  d_T[(long)ROWS * EE];

#define FULLM 0xffffffffu

// ---------------------------------------------------------------------------
// Prep: fused RZ*RY gate matrices per (layer, qubit), composed CNOT-ring perm
// ---------------------------------------------------------------------------
__global__ void prep_kernel(const float* __restrict__ theta) {
    int t = threadIdx.x;
    if (t < NL * NQ) {
        float ty = theta[t * 2 + 0];
        float tz = theta[t * 2 + 1];
        float s, c, zs, zc;
        sincosf(0.5f * ty, &s, &c);
        sincosf(0.5f * tz, &zs, &zc);
        // M = RZ(tz) @ RY(ty)
        d_gates[t * 4 + 0] = make_float2( c * zc, -c * zs);
        d_gates[t * 4 + 1] = make_float2(-s * zc,  s * zs);
        d_gates[t * 4 + 2] = make_float2( s * zc,  s * zs);
        d_gates[t * 4 + 3] = make_float2( c * zc,  c * zs);
    }
    if (t < DIMQ) {
        // Composition: new[i] = old[p0[p1[...p7[i]]]]  -> apply p7 first
        int j = t;
        #pragma unroll
        for (int q = NQ - 1; q >= 0; q--) {
            int tq   = (q + 1) & (NQ - 1);
            int cpos = NQ - 1 - q;
            int tpos = NQ - 1 - tq;
            if ((j >> cpos) & 1) j ^= (1 << tpos);
        }
        d_perm[t] = j;
    }
}

// ---------------------------------------------------------------------------
// qin = X @ Wi + bi    (16384x8, K=1024) : one warp per row
// ---------------------------------------------------------------------------
__global__ __launch_bounds__(256) void qin_kernel(const float* __restrict__ X,
                                                  const float* __restrict__ Wi,
                                                  const float* __restrict__ bi) {
    __shared__ float sWi[NQ * EE]; // transposed [o][k], 32KB
    int tid = threadIdx.x;
    for (int idx = tid; idx < EE * NQ; idx += 256) {
        int k = idx >> 3, o = idx & 7;
        sWi[o * EE + k] = Wi[idx];
    }
    __syncthreads();

    int w = tid >> 5, lane = tid & 31;
    long row = (long)blockIdx.x * 8 + w;
    const float* xr = X + row * EE;

    float acc[NQ];
    #pragma unroll
    for (int o = 0; o < NQ; o++) acc[o] = 0.f;

    for (int k = lane; k < EE; k += 32) {
        float x = xr[k];
        #pragma unroll
        for (int o = 0; o < NQ; o++) acc[o] += x * sWi[o * EE + k];
    }
    float out = 0.f;
    #pragma unroll
    for (int o = 0; o < NQ; o++) {
        float v = acc[o];
        #pragma unroll
        for (int d = 16; d > 0; d >>= 1) v += __shfl_xor_sync(FULLM, v, d);
        if (lane == o) out = v + bi[o];
    }
    if (lane < NQ) d_qin[row * NQ + lane] = out;
}

// ---------------------------------------------------------------------------
// Quantum state sim: one warp per row, state (256 complex) in shared
// ---------------------------------------------------------------------------
__global__ __launch_bounds__(256) void psi_kernel() {
    __shared__ float2 st[8][DIMQ];       // 16KB
    __shared__ float2 gm[NL * NQ * 4];   // 1KB
    __shared__ int    pm[DIMQ];          // 1KB

    int tid = threadIdx.x;
    if (tid < NL * NQ * 4) gm[tid] = d_gates[tid];
    pm[tid] = d_perm[tid];
    __syncthreads();

    int w = tid >> 5, lane = tid & 31;
    long row = (long)blockIdx.x * 8 + w;

    // initial product state from qin
    float x = (lane < NQ) ? d_qin[row * NQ + lane] : 0.f;
    float ss, cc;
    sincosf(0.5f * x, &ss, &cc);
    float cq[NQ], sq[NQ];
    #pragma unroll
    for (int q = 0; q < NQ; q++) {
        cq[q] = __shfl_sync(FULLM, cc, q);
        sq[q] = __shfl_sync(FULLM, ss, q);
    }
    #pragma unroll
    for (int j = 0; j < 8; j++) {
        int i = lane + 32 * j;
        float a = 1.f;
        #pragma unroll
        for (int q = 0; q < NQ; q++)
            a *= ((i >> (NQ - 1 - q)) & 1) ? sq[q] : cq[q];
        st[w][i] = make_float2(a, 0.f);
    }
    __syncwarp();

    for (int l = 0; l < NL; l++) {
        #pragma unroll
        for (int q = 0; q < NQ; q++) {
            const float2 m00 = gm[(l * NQ + q) * 4 + 0];
            const float2 m01 = gm[(l * NQ + q) * 4 + 1];
            const float2 m10 = gm[(l * NQ + q) * 4 + 2];
            const float2 m11 = gm[(l * NQ + q) * 4 + 3];
            int stride = 1 << (NQ - 1 - q);
            #pragma unroll
            for (int pp = 0; pp < 4; pp++) {
                int p  = lane + 32 * pp;
                int i0 = ((p & ~(stride - 1)) << 1) | (p & (stride - 1));
                int i1 = i0 | stride;
                float2 a0 = st[w][i0];
                float2 a1 = st[w][i1];
                float2 n0, n1;
                n0.x = m00.x * a0.x - m00.y * a0.y + m01.x * a1.x - m01.y * a1.y;
                n0.y = m00.x * a0.y + m00.y * a0.x + m01.x * a1.y + m01.y * a1.x;
                n1.x = m10.x * a0.x - m10.y * a0.y + m11.x * a1.x - m11.y * a1.y;
                n1.y = m10.x * a0.y + m10.y * a0.x + m11.x * a1.y + m11.y * a1.x;
                st[w][i0] = n0;
                st[w][i1] = n1;
            }
            __syncwarp();
        }
        // composed CNOT ring permutation (gather)
        float2 tmp[8];
        #pragma unroll
        for (int j = 0; j < 8; j++) tmp[j] = st[w][pm[lane + 32 * j]];
        __syncwarp();
        #pragma unroll
        for (int j = 0; j < 8; j++) st[w][lane + 32 * j] = tmp[j];
        __syncwarp();
    }
    #pragma unroll
    for (int j = 0; j < 8; j++)
        d_psi[row * DIMQ + lane + 32 * j] = st[w][lane + 32 * j];
}

// ---------------------------------------------------------------------------
// Gram + kernel-matrix + softmax -> attn.  One block per batch, 512 threads.
// Thread tile: 8 (s) x 4 (t); warp = 32 t-lanes spanning all 128 t.
// ---------------------------------------------------------------------------
__global__ __launch_bounds__(512) void gram_kernel(const float* __restrict__ phi,
                                                   float* __restrict__ attn) {
    const int DC = 16;
    __shared__ float2 P[SS][DC + 1]; // ~17.4KB

    int b   = blockIdx.x;
    int tid = threadIdx.x;
    int ts  = tid >> 5;   // 0..15 -> s rows [ts*8, ts*8+8)
    int tt  = tid & 31;   // t cols: tt + 32*k

    float accr[8][4], acci[8][4];
    #pragma unroll
    for (int j = 0; j < 8; j++)
        #pragma unroll
        for (int k = 0; k < 4; k++) { accr[j][k] = 0.f; acci[j][k] = 0.f; }

    const float2* pb = d_psi + (long)b * SS * DIMQ;

    for (int d0 = 0; d0 < DIMQ; d0 += DC) {
        #pragma unroll
        for (int u = 0; u < 4; u++) {
            int idx = tid + 512 * u;        // 0..2047
            int r = idx >> 4, dd = idx & 15;
            P[r][dd] = pb[(long)r * DIMQ + d0 + dd];
        }
        __syncthreads();
        #pragma unroll 4
        for (int dd = 0; dd < DC; dd++) {
            float2 sf[8], tf[4];
            #pragma unroll
            for (int j = 0; j < 8; j++) sf[j] = P[ts * 8 + j][dd];
            #pragma unroll
            for (int k = 0; k < 4; k++) tf[k] = P[tt + 32 * k][dd];
            #pragma unroll
            for (int j = 0; j < 8; j++)
                #pragma unroll
                for (int k = 0; k < 4; k++) {
                    accr[j][k] += sf[j].x * tf[k].x + sf[j].y * tf[k].y;
                    acci[j][k] += sf[j].y * tf[k].x - sf[j].x * tf[k].y;
                }
        }
        __syncthreads();
    }

    const float inv = 0.3535533905932738f; // 1/sqrt(8)
    float pht[4];
    #pragma unroll
    for (int k = 0; k < 4; k++) pht[k] = phi[tt + 32 * k];

    #pragma unroll
    for (int j = 0; j < 8; j++) {
        int srow = ts * 8 + j;
        float ph_s = phi[srow];
        float kv[4];
        float mx = -1e30f;
        #pragma unroll
        for (int k = 0; k < 4; k++) {
            float g2 = accr[j][k] * accr[j][k] + acci[j][k] * acci[j][k];
            kv[k] = g2 * inv + cosf(pht[k] - ph_s);
            mx = fmaxf(mx, kv[k]);
        }
        #pragma unroll
        for (int d = 16; d > 0; d >>= 1) mx = fmaxf(mx, __shfl_xor_sync(FULLM, mx, d));
        float sum = 0.f;
        #pragma unroll
        for (int k = 0; k < 4; k++) { kv[k] = expf(kv[k] - mx); sum += kv[k]; }
        #pragma unroll
        for (int d = 16; d > 0; d >>= 1) sum += __shfl_xor_sync(FULLM, sum, d);
        float is = 1.f / sum;
        #pragma unroll
        for (int k = 0; k < 4; k++)
            attn[(long)b * SS * SS + (long)srow * SS + tt + 32 * k] = kv[k] * is;
    }
}

// ---------------------------------------------------------------------------
// SGEMM: C = A@B (+bias), row-major. BM=BN=128, BK=8, TM=TN=8, 256 threads.
// Optional batching via blockIdx.z with per-batch strides.
// ---------------------------------------------------------------------------
__global__ __launch_bounds__(256) void sgemm_kernel(
    const float* __restrict__ A, const float* __restrict__ B,
    const float* __restrict__ bias, float* __restrict__ C,
    int N, int K, long sA, long sB, long sC) {
    const int BM = 128, BN = 128, BK = 8, TM = 8, TN = 8;
    __shared__ float As[BK][BM];
    __shared__ float Bs[BK][BN];

    long bz = blockIdx.z;
    A += bz * sA;
    B += bz * sB;
    C += bz * sC;

    int tid  = threadIdx.x;
    int tRow = tid >> 4;       // 0..15
    int tCol = tid & 15;       // 0..15
    int aRow = tid >> 1;       // 0..127
    int aCol = (tid & 1) * 4;  // 0 or 4
    int bRow = tid >> 5;       // 0..7
    int bCol = (tid & 31) * 4; // 0..124

    const float* Ab = A + (long)blockIdx.y * BM * K;
    const float* Bb = B + (long)blockIdx.x * BN;

    float acc[TM][TN];
    #pragma unroll
    for (int i = 0; i < TM; i++)
        #pragma unroll
        for (int j = 0; j < TN; j++) acc[i][j] = 0.f;

    for (int k0 = 0; k0 < K; k0 += BK) {
        float4 a4 = *(const float4*)(Ab + (long)aRow * K + k0 + aCol);
        As[aCol + 0][aRow] = a4.x;
        As[aCol + 1][aRow] = a4.y;
        As[aCol + 2][aRow] = a4.z;
        As[aCol + 3][aRow] = a4.w;
        float4 b4 = *(const float4*)(Bb + (long)(k0 + bRow) * N + bCol);
        *(float4*)&Bs[bRow][bCol] = b4;
        __syncthreads();
        #pragma unroll
        for (int kk = 0; kk < BK; kk++) {
            float rm[TM], rn[TN];
            *(float4*)&rm[0] = *(const float4*)&As[kk][tRow * TM];
            *(float4*)&rm[4] = *(const float4*)&As[kk][tRow * TM + 4];
            *(float4*)&rn[0] = *(const float4*)&Bs[kk][tCol * TN];
            *(float4*)&rn[4] = *(const float4*)&Bs[kk][tCol * TN + 4];
            #pragma unroll
            for (int i = 0; i < TM; i++)
                #pragma unroll
                for (int j = 0; j < TN; j++)
                    acc[i][j] += rm[i] * rn[j];
        }
        __syncthreads();
    }

    long rowBase = (long)blockIdx.y * BM + tRow * TM;
    int  colBase = blockIdx.x * BN + tCol * TN;
    #pragma unroll
    for (int i = 0; i < TM; i++) {
        #pragma unroll
        for (int j = 0; j < TN; j += 4) {
            float4 v;
            v.x = acc[i][j + 0];
            v.y = acc[i][j + 1];
            v.z = acc[i][j + 2];
            v.w = acc[i][j + 3];
            if (bias) {
                v.x += bias[colBase + j + 0];
                v.y += bias[colBase + j + 1];
                v.z += bias[colBase + j + 2];
                v.w += bias[colBase + j + 3];
            }
            *(float4*)&C[(rowBase + i) * N + colBase + j] = v;
        }
    }
}

// ---------------------------------------------------------------------------
extern "C" void kernel_launch(void* const* d_in, const int* in_sizes, int n_in,
                              void* d_out, int out_size) {
    const float* X     = (const float*)d_in[0];
    const float* Wi    = (const float*)d_in[1];
    const float* bi    = (const float*)d_in[2];
    const float* Wv    = (const float*)d_in[3];
    const float* bv    = (const float*)d_in[4];
    const float* Wo    = (const float*)d_in[5];
    const float* bo    = (const float*)d_in[6];
    const float* theta = (const float*)d_in[7];
    const float* phi   = (const float*)d_in[8];

    float* y    = (float*)d_out;
    float* attn = (float*)d_out + Y_SIZE;

    float *pV, *pT;
    cudaGetSymbolAddress((void**)&pV, d_V);
    cudaGetSymbolAddress((void**)&pT, d_T);

    // 1. gates + composed CNOT permutation
    prep_kernel<<<1, 256>>>(theta);
    // 2. qin = X@Wi + bi
    qin_kernel<<<ROWS / 8, 256>>>(X, Wi, bi);
    // 3. V = X@Wv + bv
    {
        dim3 grid(EE / 128, ROWS / 128, 1);
        sgemm_kernel<<<grid, 256>>>(X, Wv, bv, pV, EE, EE, 0, 0, 0);
    }
    // 4. quantum states
    psi_kernel<<<ROWS / 8, 256>>>();
    // 5. Gram + K + softmax -> attn (written straight into d_out)
    gram_kernel<<<NB, 512>>>(phi, attn);
    // 6. T = attn @ V   (batched: per-batch 128x1024, K=128)
    {
        dim3 grid(EE / 128, 1, NB);
        sgemm_kernel<<<grid, 256>>>(attn, pV, nullptr, pT, EE, SS,
                                    (long)SS * SS, (long)SS * EE, (long)SS * EE);
    }
    // 7. y = T @ Wo + bo
    {
        dim3 grid(EE / 128, ROWS / 128, 1);
        sgemm_kernel<<<grid, 256>>>(pT, Wo, bo, y, EE, EE, 0, 0, 0);
    }
}

// round 6
// speedup vs baseline: 1.5737x; 1.5737x over previous
#include <cuda_runtime.h>
#include <cuda_bf16.h>
#include <mma.h>
#include <math.h>
#include <stdint.h>

using namespace nvcuda;

// Problem constants (fixed shapes)
#define NB      128          // batch
#define SS      128          // seq
#define EE      1024         // embed
#define NQ      8            // qubits
#define NL      4            // layers
#define DIMQ    256          // 2^NQ
#define ROWS    16384        // NB*SS
#define KSPLIT  3072         // 3*EE (bf16 split-concat K)
#define Y_SIZE  16777216L    // NB*SS*EE

// Scratch (static device globals — allowed)
__device__ float  d_qin[ROWS * NQ];
__device__ float2 d_gates[NL * NQ * 4];
__device__ int    d_perm[DIMQ];
__device__ float2 d_psi[(long)ROWS * DIMQ];
__device__ float  d_V[(long)ROWS * EE];
__device__ float  d_T[(long)ROWS * EE];
__device__ __nv_bfloat16 d_Xs[(long)ROWS * KSPLIT];   // split X  [M][3K]
__device__ __nv_bfloat16 d_Ts[(long)ROWS * KSPLIT];   // split T  [M][3K]
__device__ __nv_bfloat16 d_Wvs[(long)EE * KSPLIT];    // split Wv^T [N][3K]
__device__ __nv_bfloat16 d_Wos[(long)EE * KSPLIT];    // split Wo^T [N][3K]

#define FULLM 0xffffffffu

// ---------------------------------------------------------------------------
// cp.async helpers (sm_80+ baseline — no 'a'-suffix features!)
// ---------------------------------------------------------------------------
__device__ __forceinline__ uint32_t smem_u32(const void* p) {
    uint32_t a;
    asm("{ .reg .u64 t; cvta.to.shared.u64 t, %1; cvt.u32.u64 %0, t; }" : "=r"(a) : "l"(p));
    return a;
}
__device__ __forceinline__ void cp16(uint32_t s, const void* g) {
    asm volatile("cp.async.cg.shared.global [%0], [%1], 16;" :: "r"(s), "l"(g));
}
#define CP_COMMIT() asm volatile("cp.async.commit_group;" ::: "memory")
#define CP_WAIT1()  asm volatile("cp.async.wait_group 1;" ::: "memory")
#define CP_WAIT0()  asm volatile("cp.async.wait_group 0;" ::: "memory")

// ---------------------------------------------------------------------------
// Prep: fused RZ*RY gate matrices, composed CNOT-ring perm
// ---------------------------------------------------------------------------
__global__ void prep_kernel(const float* __restrict__ theta) {
    int t = threadIdx.x;
    if (t < NL * NQ) {
        float ty = theta[t * 2 + 0];
        float tz = theta[t * 2 + 1];
        float s, c, zs, zc;
        sincosf(0.5f * ty, &s, &c);
        sincosf(0.5f * tz, &zs, &zc);
        d_gates[t * 4 + 0] = make_float2( c * zc, -c * zs);
        d_gates[t * 4 + 1] = make_float2(-s * zc,  s * zs);
        d_gates[t * 4 + 2] = make_float2( s * zc,  s * zs);
        d_gates[t * 4 + 3] = make_float2( c * zc,  c * zs);
    }
    if (t < DIMQ) {
        int j = t;
        #pragma unroll
        for (int q = NQ - 1; q >= 0; q--) {
            int tq   = (q + 1) & (NQ - 1);
            int cpos = NQ - 1 - q;
            int tpos = NQ - 1 - tq;
            if ((j >> cpos) & 1) j ^= (1 << tpos);
        }
        d_perm[t] = j;
    }
}

// ---------------------------------------------------------------------------
// splitA: fp32 [R x 1024] -> bf16 [R x 3072] laid out [hi | lo | hi]
// ---------------------------------------------------------------------------
__global__ __launch_bounds__(256) void splitA_kernel(const float* __restrict__ src,
                                                     __nv_bfloat16* __restrict__ dst) {
    long i = (long)blockIdx.x * 256 + threadIdx.x;   // float4 index
    float4 v = ((const float4*)src)[i];
    long r  = i >> 8;
    int  c4 = (int)(i & 255) * 4;
    float vv[4] = {v.x, v.y, v.z, v.w};
    union { __nv_bfloat16 b[4]; uint2 u; } H, L;
    #pragma unroll
    for (int j = 0; j < 4; j++) {
        __nv_bfloat16 h = __float2bfloat16(vv[j]);
        H.b[j] = h;
        L.b[j] = __float2bfloat16(vv[j] - __bfloat162float(h));
    }
    __nv_bfloat16* row = dst + r * KSPLIT;
    *(uint2*)(row + c4)        = H.u;
    *(uint2*)(row + EE + c4)   = L.u;
    *(uint2*)(row + 2*EE + c4) = H.u;
}

// ---------------------------------------------------------------------------
// splitB: W fp32 [K=1024][N=1024] -> Bt bf16 [N][3072] = [hi | hi | lo] transposed
// ---------------------------------------------------------------------------
__global__ __launch_bounds__(256) void splitB_kernel(const float* __restrict__ W,
                                                     __nv_bfloat16* __restrict__ Bt) {
    __shared__ float tile[32][33];
    int k0 = blockIdx.y * 32, n0 = blockIdx.x * 32;
    int tx = threadIdx.x & 31, ty = threadIdx.x >> 5;  // 32 x 8
    #pragma unroll
    for (int j = 0; j < 32; j += 8)
        tile[ty + j][tx] = W[(long)(k0 + ty + j) * EE + n0 + tx];
    __syncthreads();
    #pragma unroll
    for (int j = 0; j < 32; j += 8) {
        int n = n0 + ty + j, k = k0 + tx;
        float v = tile[tx][ty + j];
        __nv_bfloat16 h = __float2bfloat16(v);
        __nv_bfloat16 l = __float2bfloat16(v - __bfloat162float(h));
        __nv_bfloat16* row = Bt + (long)n * KSPLIT;
        row[k]          = h;
        row[EE + k]     = h;
        row[2*EE + k]   = l;
    }
}

// ---------------------------------------------------------------------------
// wmma (HMMA) GEMM: C[M,1024] = A'[M,3072] x Bt'[1024,3072]^T + bias
// BM=BN=128, BK=32, 256 threads (8 warps, 4x2), double-buffered cp.async.
// Warp tile 32x64 via 2x4 fragments of 16x16x16 bf16.
// ---------------------------------------------------------------------------
#define WG_LDS   40                  // smem row stride (bf16 elems), 80 bytes
#define WG_ABUF  (128 * WG_LDS * 2)  // 10240 bytes per A tile
#define WG_NCH   (KSPLIT / 32)       // 96 chunks

__global__ __launch_bounds__(256) void wgemm_kernel(
    const __nv_bfloat16* __restrict__ A, const __nv_bfloat16* __restrict__ B,
    const float* __restrict__ bias, float* __restrict__ C) {
    __shared__ __align__(16) char smem_raw[4 * WG_ABUF];  // A0,B0,A1,B1 = 40960 B
    uint32_t sbase = smem_u32(smem_raw);

    int tid  = threadIdx.x;
    int wid  = tid >> 5, lane = tid & 31;
    int wm   = wid & 3;         // warp row:  rows [wm*32, wm*32+32)
    int wn   = wid >> 2;        // warp col:  cols [wn*64, wn*64+64)

    long m0 = (long)blockIdx.y * 128;
    int  n0 = blockIdx.x * 128;

    // cp.async mapping: 2 x 16B for A + 2 x 16B for B per thread per chunk.
    // A tile 128x32 bf16 = 512 x 16B segs; idx = tid + 256u -> row=idx>>2, seg=idx&3
    uint32_t dstA[2], dstB[2];
    const char* srcA[2];
    const char* srcB[2];
    #pragma unroll
    for (int u = 0; u < 2; u++) {
        int idx = tid + 256 * u;
        int row = idx >> 2, seg = idx & 3;
        uint32_t d = (uint32_t)row * (WG_LDS * 2) + seg * 16;
        dstA[u] = d;
        dstB[u] = d;
        srcA[u] = (const char*)(A + (m0 + row) * (long)KSPLIT) + seg * 16;
        srcB[u] = (const char*)(B + (long)(n0 + row) * KSPLIT) + seg * 16;
    }

    wmma::fragment<wmma::accumulator, 16, 16, 16, float> acc[2][4];
    #pragma unroll
    for (int i = 0; i < 2; i++)
        #pragma unroll
        for (int j = 0; j < 4; j++) wmma::fill_fragment(acc[i][j], 0.f);

    // prologue: chunk 0 -> buf 0
    {
        uint32_t a0 = sbase, b0 = sbase + WG_ABUF;
        #pragma unroll
        for (int u = 0; u < 2; u++) {
            cp16(a0 + dstA[u], srcA[u]);
            cp16(b0 + dstB[u], srcB[u]);
        }
        CP_COMMIT();
    }

    #pragma unroll 1
    for (int ch = 0; ch < WG_NCH; ch++) {
        if (ch + 1 < WG_NCH) {
            uint32_t off = ((ch + 1) & 1) ? 2u * WG_ABUF : 0u;
            uint32_t an = sbase + off, bn = sbase + off + WG_ABUF;
            long gofs = (long)(ch + 1) * 64;   // 32 bf16 = 64 bytes per chunk
            #pragma unroll
            for (int u = 0; u < 2; u++) {
                cp16(an + dstA[u], srcA[u] + gofs);
                cp16(bn + dstB[u], srcB[u] + gofs);
            }
            CP_COMMIT();
            CP_WAIT1();
        } else {
            CP_WAIT0();
        }
        __syncthreads();

        const __nv_bfloat16* bufA =
            (const __nv_bfloat16*)(smem_raw + ((ch & 1) ? 2 * WG_ABUF : 0));
        const __nv_bfloat16* bufB = bufA + 128 * WG_LDS;

        #pragma unroll
        for (int kk = 0; kk < 32; kk += 16) {
            wmma::fragment<wmma::matrix_a, 16, 16, 16, __nv_bfloat16, wmma::row_major> af[2];
            wmma::fragment<wmma::matrix_b, 16, 16, 16, __nv_bfloat16, wmma::col_major> bf[4];
            #pragma unroll
            for (int i = 0; i < 2; i++)
                wmma::load_matrix_sync(af[i], bufA + (wm * 32 + i * 16) * WG_LDS + kk, WG_LDS);
            #pragma unroll
            for (int j = 0; j < 4; j++)
                wmma::load_matrix_sync(bf[j], bufB + (wn * 64 + j * 16) * WG_LDS + kk, WG_LDS);
            #pragma unroll
            for (int i = 0; i < 2; i++)
                #pragma unroll
                for (int j = 0; j < 4; j++)
                    wmma::mma_sync(acc[i][j], af[i], bf[j], acc[i][j]);
        }
        __syncthreads();
    }

    // Epilogue: per-warp SMEM staging (16x68 f32) -> coalesced STG + bias
    float* stag = (float*)smem_raw + wid * (16 * 68);
    int erow = lane >> 1, ecb = (lane & 1) * 32;
    #pragma unroll
    for (int mi = 0; mi < 2; mi++) {
        #pragma unroll
        for (int j = 0; j < 4; j++)
            wmma::store_matrix_sync(stag + j * 16, acc[mi][j], 68, wmma::mem_row_major);
        __syncwarp();
        long grow = m0 + wm * 32 + mi * 16 + erow;
        int  gcol = n0 + wn * 64 + ecb;
        #pragma unroll
        for (int f = 0; f < 8; f++) {
            float4 v  = *(float4*)(stag + erow * 68 + ecb + f * 4);
            float4 b4 = *(const float4*)(bias + gcol + f * 4);
            v.x += b4.x; v.y += b4.y; v.z += b4.z; v.w += b4.w;
            *(float4*)(C + grow * EE + gcol + f * 4) = v;
        }
        __syncwarp();
    }
}

// ---------------------------------------------------------------------------
// qin = X @ Wi + bi    (16384x8, K=1024) : one warp per row
// ---------------------------------------------------------------------------
__global__ __launch_bounds__(256) void qin_kernel(const float* __restrict__ X,
                                                  const float* __restrict__ Wi,
                                                  const float* __restrict__ bi) {
    __shared__ float sWi[NQ * EE];
    int tid = threadIdx.x;
    for (int idx = tid; idx < EE * NQ; idx += 256) {
        int k = idx >> 3, o = idx & 7;
        sWi[o * EE + k] = Wi[idx];
    }
    __syncthreads();

    int w = tid >> 5, lane = tid & 31;
    long row = (long)blockIdx.x * 8 + w;
    const float* xr = X + row * EE;

    float acc[NQ];
    #pragma unroll
    for (int o = 0; o < NQ; o++) acc[o] = 0.f;
    for (int k = lane; k < EE; k += 32) {
        float x = xr[k];
        #pragma unroll
        for (int o = 0; o < NQ; o++) acc[o] += x * sWi[o * EE + k];
    }
    float out = 0.f;
    #pragma unroll
    for (int o = 0; o < NQ; o++) {
        float v = acc[o];
        #pragma unroll
        for (int d = 16; d > 0; d >>= 1) v += __shfl_xor_sync(FULLM, v, d);
        if (lane == o) out = v + bi[o];
    }
    if (lane < NQ) d_qin[row * NQ + lane] = out;
}

// ---------------------------------------------------------------------------
// Quantum state sim: one warp per row, state (256 complex) in shared
// ---------------------------------------------------------------------------
__global__ __launch_bounds__(256) void psi_kernel() {
    __shared__ float2 st[8][DIMQ];
    __shared__ float2 gm[NL * NQ * 4];
    __shared__ int    pm[DIMQ];

    int tid = threadIdx.x;
    if (tid < NL * NQ * 4) gm[tid] = d_gates[tid];
    pm[tid] = d_perm[tid];
    __syncthreads();

    int w = tid >> 5, lane = tid & 31;
    long row = (long)blockIdx.x * 8 + w;

    float x = (lane < NQ) ? d_qin[row * NQ + lane] : 0.f;
    float ss, cc;
    sincosf(0.5f * x, &ss, &cc);
    float cq[NQ], sq[NQ];
    #pragma unroll
    for (int q = 0; q < NQ; q++) {
        cq[q] = __shfl_sync(FULLM, cc, q);
        sq[q] = __shfl_sync(FULLM, ss, q);
    }
    #pragma unroll
    for (int j = 0; j < 8; j++) {
        int i = lane + 32 * j;
        float a = 1.f;
        #pragma unroll
        for (int q = 0; q < NQ; q++)
            a *= ((i >> (NQ - 1 - q)) & 1) ? sq[q] : cq[q];
        st[w][i] = make_float2(a, 0.f);
    }
    __syncwarp();

    for (int l = 0; l < NL; l++) {
        #pragma unroll
        for (int q = 0; q < NQ; q++) {
            const float2 m00 = gm[(l * NQ + q) * 4 + 0];
            const float2 m01 = gm[(l * NQ + q) * 4 + 1];
            const float2 m10 = gm[(l * NQ + q) * 4 + 2];
            const float2 m11 = gm[(l * NQ + q) * 4 + 3];
            int stride = 1 << (NQ - 1 - q);
            #pragma unroll
            for (int pp = 0; pp < 4; pp++) {
                int p  = lane + 32 * pp;
                int i0 = ((p & ~(stride - 1)) << 1) | (p & (stride - 1));
                int i1 = i0 | stride;
                float2 a0 = st[w][i0];
                float2 a1 = st[w][i1];
                float2 n0, n1;
                n0.x = m00.x * a0.x - m00.y * a0.y + m01.x * a1.x - m01.y * a1.y;
                n0.y = m00.x * a0.y + m00.y * a0.x + m01.x * a1.y + m01.y * a1.x;
                n1.x = m10.x * a0.x - m10.y * a0.y + m11.x * a1.x - m11.y * a1.y;
                n1.y = m10.x * a0.y + m10.y * a0.x + m11.x * a1.y + m11.y * a1.x;
                st[w][i0] = n0;
                st[w][i1] = n1;
            }
            __syncwarp();
        }
        float2 tmp[8];
        #pragma unroll
        for (int j = 0; j < 8; j++) tmp[j] = st[w][pm[lane + 32 * j]];
        __syncwarp();
        #pragma unroll
        for (int j = 0; j < 8; j++) st[w][lane + 32 * j] = tmp[j];
        __syncwarp();
    }
    #pragma unroll
    for (int j = 0; j < 8; j++)
        d_psi[row * DIMQ + lane + 32 * j] = st[w][lane + 32 * j];
}

// ---------------------------------------------------------------------------
// Gram + kernel-matrix + softmax -> attn.  One block per batch, 512 threads.
// ---------------------------------------------------------------------------
__global__ __launch_bounds__(512) void gram_kernel(const float* __restrict__ phi,
                                                   float* __restrict__ attn) {
    const int DC = 16;
    __shared__ float2 P[SS][DC + 1];

    int b   = blockIdx.x;
    int tid = threadIdx.x;
    int ts  = tid >> 5;
    int tt  = tid & 31;

    float accr[8][4], acci[8][4];
    #pragma unroll
    for (int j = 0; j < 8; j++)
        #pragma unroll
        for (int k = 0; k < 4; k++) { accr[j][k] = 0.f; acci[j][k] = 0.f; }

    const float2* pb = d_psi + (long)b * SS * DIMQ;

    for (int d0 = 0; d0 < DIMQ; d0 += DC) {
        #pragma unroll
        for (int u = 0; u < 4; u++) {
            int idx = tid + 512 * u;
            int r = idx >> 4, dd = idx & 15;
            P[r][dd] = pb[(long)r * DIMQ + d0 + dd];
        }
        __syncthreads();
        #pragma unroll 4
        for (int dd = 0; dd < DC; dd++) {
            float2 sf[8], tf[4];
            #pragma unroll
            for (int j = 0; j < 8; j++) sf[j] = P[ts * 8 + j][dd];
            #pragma unroll
            for (int k = 0; k < 4; k++) tf[k] = P[tt + 32 * k][dd];
            #pragma unroll
            for (int j = 0; j < 8; j++)
                #pragma unroll
                for (int k = 0; k < 4; k++) {
                    accr[j][k] += sf[j].x * tf[k].x + sf[j].y * tf[k].y;
                    acci[j][k] += sf[j].y * tf[k].x - sf[j].x * tf[k].y;
                }
        }
        __syncthreads();
    }

    const float inv = 0.3535533905932738f;
    float pht[4];
    #pragma unroll
    for (int k = 0; k < 4; k++) pht[k] = phi[tt + 32 * k];

    #pragma unroll
    for (int j = 0; j < 8; j++) {
        int srow = ts * 8 + j;
        float ph_s = phi[srow];
        float kv[4];
        float mx = -1e30f;
        #pragma unroll
        for (int k = 0; k < 4; k++) {
            float g2 = accr[j][k] * accr[j][k] + acci[j][k] * acci[j][k];
            kv[k] = g2 * inv + cosf(pht[k] - ph_s);
            mx = fmaxf(mx, kv[k]);
        }
        #pragma unroll
        for (int d = 16; d > 0; d >>= 1) mx = fmaxf(mx, __shfl_xor_sync(FULLM, mx, d));
        float sum = 0.f;
        #pragma unroll
        for (int k = 0; k < 4; k++) { kv[k] = expf(kv[k] - mx); sum += kv[k]; }
        #pragma unroll
        for (int d = 16; d > 0; d >>= 1) sum += __shfl_xor_sync(FULLM, sum, d);
        float is = 1.f / sum;
        #pragma unroll
        for (int k = 0; k < 4; k++)
            attn[(long)b * SS * SS + (long)srow * SS + tt + 32 * k] = kv[k] * is;
    }
}

// ---------------------------------------------------------------------------
// SGEMM (for attn@V only): BM=BN=128, BK=8, TM=TN=8, 256 threads, batched.
// ---------------------------------------------------------------------------
__global__ __launch_bounds__(256) void sgemm_kernel(
    const float* __restrict__ A, const float* __restrict__ B,
    const float* __restrict__ bias, float* __restrict__ C,
    int N, int K, long sA, long sB, long sC) {
    const int BM = 128, BN = 128, BK = 8, TM = 8, TN = 8;
    __shared__ float As[BK][BM];
    __shared__ float Bs[BK][BN];

    long bz = blockIdx.z;
    A += bz * sA;
    B += bz * sB;
    C += bz * sC;

    int tid  = threadIdx.x;
    int tRow = tid >> 4;
    int tCol = tid & 15;
    int aRow = tid >> 1;
    int aCol = (tid & 1) * 4;
    int bRow = tid >> 5;
    int bCol = (tid & 31) * 4;

    const float* Ab = A + (long)blockIdx.y * BM * K;
    const float* Bb = B + (long)blockIdx.x * BN;

    float acc[TM][TN];
    #pragma unroll
    for (int i = 0; i < TM; i++)
        #pragma unroll
        for (int j = 0; j < TN; j++) acc[i][j] = 0.f;

    for (int k0 = 0; k0 < K; k0 += BK) {
        float4 a4 = *(const float4*)(Ab + (long)aRow * K + k0 + aCol);
        As[aCol + 0][aRow] = a4.x;
        As[aCol + 1][aRow] = a4.y;
        As[aCol + 2][aRow] = a4.z;
        As[aCol + 3][aRow] = a4.w;
        float4 b4 = *(const float4*)(Bb + (long)(k0 + bRow) * N + bCol);
        *(float4*)&Bs[bRow][bCol] = b4;
        __syncthreads();
        #pragma unroll
        for (int kk = 0; kk < BK; kk++) {
            float rm[TM], rn[TN];
            *(float4*)&rm[0] = *(const float4*)&As[kk][tRow * TM];
            *(float4*)&rm[4] = *(const float4*)&As[kk][tRow * TM + 4];
            *(float4*)&rn[0] = *(const float4*)&Bs[kk][tCol * TN];
            *(float4*)&rn[4] = *(const float4*)&Bs[kk][tCol * TN + 4];
            #pragma unroll
            for (int i = 0; i < TM; i++)
                #pragma unroll
                for (int j = 0; j < TN; j++)
                    acc[i][j] += rm[i] * rn[j];
        }
        __syncthreads();
    }

    long rowBase = (long)blockIdx.y * BM + tRow * TM;
    int  colBase = blockIdx.x * BN + tCol * TN;
    #pragma unroll
    for (int i = 0; i < TM; i++) {
        #pragma unroll
        for (int j = 0; j < TN; j += 4) {
            float4 v;
            v.x = acc[i][j + 0];
            v.y = acc[i][j + 1];
            v.z = acc[i][j + 2];
            v.w = acc[i][j + 3];
            if (bias) {
                v.x += bias[colBase + j + 0];
                v.y += bias[colBase + j + 1];
                v.z += bias[colBase + j + 2];
                v.w += bias[colBase + j + 3];
            }
            *(float4*)&C[(rowBase + i) * N + colBase + j] = v;
        }
    }
}

// ---------------------------------------------------------------------------
extern "C" void kernel_launch(void* const* d_in, const int* in_sizes, int n_in,
                              void* d_out, int out_size) {
    const float* X     = (const float*)d_in[0];
    const float* Wi    = (const float*)d_in[1];
    const float* bi    = (const float*)d_in[2];
    const float* Wv    = (const float*)d_in[3];
    const float* bv    = (const float*)d_in[4];
    const float* Wo    = (const float*)d_in[5];
    const float* bo    = (const float*)d_in[6];
    const float* theta = (const float*)d_in[7];
    const float* phi   = (const float*)d_in[8];

    float* y    = (float*)d_out;
    float* attn = (float*)d_out + Y_SIZE;

    float *pV, *pT;
    __nv_bfloat16 *pXs, *pTs, *pWvs, *pWos;
    cudaGetSymbolAddress((void**)&pV, d_V);
    cudaGetSymbolAddress((void**)&pT, d_T);
    cudaGetSymbolAddress((void**)&pXs, d_Xs);
    cudaGetSymbolAddress((void**)&pTs, d_Ts);
    cudaGetSymbolAddress((void**)&pWvs, d_Wvs);
    cudaGetSymbolAddress((void**)&pWos, d_Wos);

    // prep + splits
    prep_kernel<<<1, 256>>>(theta);
    {
        dim3 g(EE / 32, EE / 32);
        splitB_kernel<<<g, 256>>>(Wv, pWvs);
        splitB_kernel<<<g, 256>>>(Wo, pWos);
    }
    splitA_kernel<<<ROWS, 256>>>(X, pXs);
    qin_kernel<<<ROWS / 8, 256>>>(X, Wi, bi);

    // V = X@Wv + bv  (tensor cores via wmma/HMMA)
    {
        dim3 grid(EE / 128, ROWS / 128);
        wgemm_kernel<<<grid, 256>>>(pXs, pWvs, bv, pV);
    }

    // quantum states + Gram/softmax
    psi_kernel<<<ROWS / 8, 256>>>();
    gram_kernel<<<NB, 512>>>(phi, attn);

    // T = attn @ V (batched SIMT, K=128)
    {
        dim3 grid(EE / 128, 1, NB);
        sgemm_kernel<<<grid, 256>>>(attn, pV, nullptr, pT, EE, SS,
                                    (long)SS * SS, (long)SS * EE, (long)SS * EE);
    }
    // split T, then y = T@Wo + bo (tensor cores via wmma/HMMA)
    splitA_kernel<<<ROWS, 256>>>(pT, pTs);
    {
        dim3 grid(EE / 128, ROWS / 128);
        wgemm_kernel<<<grid, 256>>>(pTs, pWos, bo, y);
    }
}